// round 15
// baseline (speedup 1.0000x reference)
#include <cuda_runtime.h>
#include <cuda_bf16.h>
#include <cuda_fp16.h>
#include <stdint.h>
#include <math.h>

// Problem constants
#define NTOK 4096
#define DD   1024
#define EE   8
#define HH   2048
#define CAP  4096

// GEMM tiling
#define BM 128
#define BN 128
#define BK 64
#define LDAS 72          // BK + 8 pad (fp16 elems); 144B rows -> conflict-free ldmatrix
#define LDBS 136         // BN + 8 pad; 272B rows -> conflict-free ldmatrix
#define NT 256
#define NSTG 3
#define ASTB (BM * LDAS * 2)   // 18432 B per A stage
#define BSTB (BK * LDBS * 2)   // 17408 B per B stage
#define SMEM_DYN (NSTG * (ASTB + BSTB))   // 107520 B

// Router
#define RTB 512
#define WRD (DD + 4)

// ---------------- static scratch (no allocations allowed) ----------------
__device__ int   g_cnt[EE];
__device__ int   g_tok[EE * CAP];
__device__ float g_gate[EE * CAP];
__device__ __half g_xf[(size_t)NTOK * DD];          // 8 MB
__device__ __half g_w1f[(size_t)EE * DD * HH];      // 32 MB
__device__ __half g_w2f[(size_t)EE * HH * DD];      // 32 MB
__device__ __half g_hf[(size_t)EE * CAP * HH];      // 128 MB

// ---------------- tiny kernels ----------------
// Zero output (graph replays must not accumulate) + expert counters.
__global__ void k_zout(float* __restrict__ out) {
    int i = blockIdx.x * blockDim.x + threadIdx.x;
    reinterpret_cast<float4*>(out)[i] = make_float4(0.f, 0.f, 0.f, 0.f);
    if (blockIdx.x == 0 && threadIdx.x < EE) g_cnt[threadIdx.x] = 0;
}

// fp32 -> fp16 conversion for BOTH weight tensors in one launch.
__global__ void k_cvtw(const float* __restrict__ W1, const float* __restrict__ W2) {
    const int n1 = EE * DD * HH / 4;           // float4 count per tensor
    int i = blockIdx.x * blockDim.x + threadIdx.x;
    int stride = gridDim.x * blockDim.x;
    for (; i < 2 * n1; i += stride) {
        const float* src = (i < n1) ? W1 : W2;
        __half* dst = (i < n1) ? g_w1f : g_w2f;
        int j = (i < n1) ? i : i - n1;
        float4 v = reinterpret_cast<const float4*>(src)[j];
        __half2 lo = __float22half2_rn(make_float2(v.x, v.y));
        __half2 hi = __float22half2_rn(make_float2(v.z, v.w));
        uint2 o;
        o.x = *reinterpret_cast<uint32_t*>(&lo);
        o.y = *reinterpret_cast<uint32_t*>(&hi);
        reinterpret_cast<uint2*>(dst)[j] = o;
    }
}

// Router: warp per token; Wr staged transposed in smem (conflict-free LDS.128).
__global__ __launch_bounds__(RTB) void k_router(const float* __restrict__ x,
                                                const float* __restrict__ Wr,
                                                const float* __restrict__ br) {
    __shared__ float wrt[EE * WRD];
    const int tid = threadIdx.x;

    for (int idx = tid; idx < DD * EE / 4; idx += RTB) {
        float4 v = reinterpret_cast<const float4*>(Wr)[idx];
        int d = idx >> 1, eb = (idx & 1) * 4;
        wrt[(eb + 0) * WRD + d] = v.x;
        wrt[(eb + 1) * WRD + d] = v.y;
        wrt[(eb + 2) * WRD + d] = v.z;
        wrt[(eb + 3) * WRD + d] = v.w;
    }
    __syncthreads();

    const int t = blockIdx.x * (RTB / 32) + (tid >> 5);
    const int lane = tid & 31;
    const float4* xr = reinterpret_cast<const float4*>(x + (size_t)t * DD);
    uint2* xo = reinterpret_cast<uint2*>(g_xf + (size_t)t * DD);

    float acc[EE];
    #pragma unroll
    for (int e = 0; e < EE; e++) acc[e] = 0.f;

    #pragma unroll
    for (int i = 0; i < 8; i++) {
        const int c = lane + i * 32;
        float4 v = xr[c];
        __half2 lo = __float22half2_rn(make_float2(v.x, v.y));
        __half2 hi = __float22half2_rn(make_float2(v.z, v.w));
        uint2 o;
        o.x = *reinterpret_cast<uint32_t*>(&lo);
        o.y = *reinterpret_cast<uint32_t*>(&hi);
        xo[c] = o;
        #pragma unroll
        for (int e = 0; e < EE; e++) {
            const float4 wv = *reinterpret_cast<const float4*>(&wrt[e * WRD + c * 4]);
            acc[e] = fmaf(v.x, wv.x, acc[e]);
            acc[e] = fmaf(v.y, wv.y, acc[e]);
            acc[e] = fmaf(v.z, wv.z, acc[e]);
            acc[e] = fmaf(v.w, wv.w, acc[e]);
        }
    }
    #pragma unroll
    for (int off = 16; off; off >>= 1)
        #pragma unroll
        for (int e = 0; e < EE; e++)
            acc[e] += __shfl_xor_sync(0xffffffffu, acc[e], off);

    if (lane == 0) {
        #pragma unroll
        for (int e = 0; e < EE; e++) acc[e] += br[e];
        float v0 = -3.4e38f; int i0 = 0;
        #pragma unroll
        for (int e = 0; e < EE; e++) if (acc[e] > v0) { v0 = acc[e]; i0 = e; }
        float v1 = -3.4e38f; int i1 = 0;
        #pragma unroll
        for (int e = 0; e < EE; e++) if (e != i0 && acc[e] > v1) { v1 = acc[e]; i1 = e; }
        float eb  = expf(v1 - v0);
        float inv = 1.f / (1.f + eb);
        int p0 = atomicAdd(&g_cnt[i0], 1);
        g_tok[i0 * CAP + p0] = t; g_gate[i0 * CAP + p0] = inv;
        int p1 = atomicAdd(&g_cnt[i1], 1);
        g_tok[i1 * CAP + p1] = t; g_gate[i1 * CAP + p1] = eb * inv;
    }
}

// ---------------- asm helpers ----------------
__device__ __forceinline__ void mma_f16(float c[4], const uint32_t a[4], const uint32_t b[2]) {
    asm volatile(
        "mma.sync.aligned.m16n8k16.row.col.f32.f16.f16.f32 "
        "{%0,%1,%2,%3}, {%4,%5,%6,%7}, {%8,%9}, {%0,%1,%2,%3};\n"
        : "+f"(c[0]), "+f"(c[1]), "+f"(c[2]), "+f"(c[3])
        : "r"(a[0]), "r"(a[1]), "r"(a[2]), "r"(a[3]), "r"(b[0]), "r"(b[1]));
}
__device__ __forceinline__ void ldsm_x4(uint32_t r[4], uint32_t addr) {
    asm volatile("ldmatrix.sync.aligned.m8n8.x4.shared.b16 {%0,%1,%2,%3}, [%4];\n"
        : "=r"(r[0]), "=r"(r[1]), "=r"(r[2]), "=r"(r[3]) : "r"(addr));
}
__device__ __forceinline__ void ldsm_x4_t(uint32_t r[4], uint32_t addr) {
    asm volatile("ldmatrix.sync.aligned.m8n8.x4.trans.shared.b16 {%0,%1,%2,%3}, [%4];\n"
        : "=r"(r[0]), "=r"(r[1]), "=r"(r[2]), "=r"(r[3]) : "r"(addr));
}
__device__ __forceinline__ void cp16(uint32_t dst, const void* src) {
    asm volatile("cp.async.cg.shared.global [%0], [%1], 16;\n" :: "r"(dst), "l"(src));
}
__device__ __forceinline__ void cp16z(uint32_t dst, const void* src, uint32_t sz) {
    asm volatile("cp.async.cg.shared.global [%0], [%1], 16, %2;\n" :: "r"(dst), "l"(src), "r"(sz));
}
__device__ __forceinline__ void red_v2(float* addr, float v0, float v1) {
    asm volatile("red.global.add.v2.f32 [%0], {%1, %2};\n"
        :: "l"(addr), "f"(v0), "f"(v1) : "memory");
}
#define CP_COMMIT() asm volatile("cp.async.commit_group;\n")
#define CP_WAIT1()  asm volatile("cp.async.wait_group 1;\n")

// ---------------- GEMM1: H = relu(Xg @ W1 + b1), fp16 MMA, BK=64 3-stage pipe ----------------
__global__ __launch_bounds__(NT, 2) void k_gemm1(const float* __restrict__ b1) {
    const int e   = blockIdx.z;
    const int cnt = g_cnt[e];
    const int mb  = blockIdx.y * BM;
    if (mb >= cnt) return;
    const int nb  = blockIdx.x * BN;

    extern __shared__ char dynsmem[];
    const uint32_t sA = (uint32_t)__cvta_generic_to_shared(dynsmem);
    const uint32_t sB = sA + NSTG * ASTB;
    __shared__ int stok[BM];

    const int tid = threadIdx.x;
    if (tid < BM) {
        int m = mb + tid;
        stok[tid] = (m < cnt) ? g_tok[e * CAP + m] : -1;
    }
    __syncthreads();

    // loader coords: A: 2 thr/row, 4x16B each (64 elems/row); B: 4 thr/row, 4x16B each
    const int a_row = tid >> 1;
    const int a_col = (tid & 1) * 32;
    const int b_kr  = tid >> 2;
    const int b_nc  = (tid & 3) * 32;
    const int atok  = stok[a_row];
    const uint32_t a_sz = (atok >= 0) ? 16u : 0u;
    const __half* agp = g_xf + (atok >= 0 ? (size_t)atok * DD + a_col : 0);
    const __half* wbp = g_w1f + (size_t)e * DD * HH + (size_t)b_kr * HH + nb + b_nc;
    const uint32_t aoff = (a_row * LDAS + a_col) * 2;
    const uint32_t boff = (b_kr * LDBS + b_nc) * 2;

    // fragment coords: 8 warps as 2(m) x 4(n); warp tile 64x32
    const int w = tid >> 5, lane = tid & 31;
    const int wm = (w >> 2) * 64, wn = (w & 3) * 32;
    const int g = lane >> 2, tq = lane & 3;
    const int alr = lane & 15, ahc = (lane >> 4) * 8;
    uint32_t aoffs[4], boffs[2];
    #pragma unroll
    for (int mf = 0; mf < 4; mf++)
        aoffs[mf] = ((wm + mf * 16 + alr) * LDAS + ahc) * 2;
    #pragma unroll
    for (int ns = 0; ns < 2; ns++)
        boffs[ns] = (alr * LDBS + wn + ns * 16 + ahc) * 2;

    float acc[4][4][4];
    #pragma unroll
    for (int a = 0; a < 4; a++)
        #pragma unroll
        for (int b = 0; b < 4; b++)
            #pragma unroll
            for (int c = 0; c < 4; c++) acc[a][b][c] = 0.f;

    const int NS = DD / BK;   // 16
    #pragma unroll
    for (int p = 0; p < NSTG - 1; p++) {
        const int kt = p * BK;
        const uint32_t ao = p * ASTB + aoff, bo = p * BSTB + boff;
        #pragma unroll
        for (int q = 0; q < 4; q++) {
            cp16z(sA + ao + q * 16, agp + kt + q * 8, a_sz);
            cp16(sB + bo + q * 16, wbp + (size_t)kt * HH + q * 8);
        }
        CP_COMMIT();
    }
    int buf = 0;
    for (int s = 0; s < NS; s++) {
        CP_WAIT1();
        __syncthreads();
        if (s + NSTG - 1 < NS) {
            const int p = s + NSTG - 1;
            const int kt = p * BK;
            int pb = p % NSTG;
            const uint32_t ao = pb * ASTB + aoff, bo = pb * BSTB + boff;
            #pragma unroll
            for (int q = 0; q < 4; q++) {
                cp16z(sA + ao + q * 16, agp + kt + q * 8, a_sz);
                cp16(sB + bo + q * 16, wbp + (size_t)kt * HH + q * 8);
            }
        }
        CP_COMMIT();

        const uint32_t Ab = sA + buf * ASTB;
        const uint32_t Bb = sB + buf * BSTB;
        #pragma unroll
        for (int kk = 0; kk < BK; kk += 16) {
            uint32_t ah[4][4], bfr[2][4];
            #pragma unroll
            for (int mf = 0; mf < 4; mf++) ldsm_x4(ah[mf], Ab + aoffs[mf] + kk * 2);
            #pragma unroll
            for (int ns = 0; ns < 2; ns++) ldsm_x4_t(bfr[ns], Bb + boffs[ns] + kk * (LDBS * 2));
            #pragma unroll
            for (int mf = 0; mf < 4; mf++)
                #pragma unroll
                for (int nf = 0; nf < 4; nf++)
                    mma_f16(acc[mf][nf], ah[mf], &bfr[nf >> 1][(nf & 1) * 2]);
        }
        if (++buf == NSTG) buf = 0;
    }

    // epilogue: +b1, relu, store fp16 h
    #pragma unroll
    for (int mf = 0; mf < 4; mf++) {
        #pragma unroll
        for (int rr = 0; rr < 2; rr++) {
            int m = mb + wm + mf * 16 + g + rr * 8;
            if (m >= cnt) continue;
            size_t base = ((size_t)e * CAP + m) * HH + nb;
            #pragma unroll
            for (int nf = 0; nf < 4; nf++) {
                int c = wn + nf * 8 + 2 * tq;
                float v0 = fmaxf(acc[mf][nf][rr * 2 + 0] + b1[e * HH + nb + c], 0.f);
                float v1 = fmaxf(acc[mf][nf][rr * 2 + 1] + b1[e * HH + nb + c + 1], 0.f);
                __half2 pr = __float22half2_rn(make_float2(v0, v1));
                *reinterpret_cast<__half2*>(&g_hf[base + c]) = pr;
            }
        }
    }
}

// ---------------- GEMM2: out += gate * (H @ W2 + b2), fp16 MMA, BK=64 3-stage pipe ----------------
__global__ __launch_bounds__(NT, 2) void k_gemm2(const float* __restrict__ b2,
                                                 float* __restrict__ out) {
    const int e   = blockIdx.z;
    const int cnt = g_cnt[e];
    const int mb  = blockIdx.y * BM;
    if (mb >= cnt) return;
    const int nb  = blockIdx.x * BN;

    extern __shared__ char dynsmem[];
    const uint32_t sA = (uint32_t)__cvta_generic_to_shared(dynsmem);
    const uint32_t sB = sA + NSTG * ASTB;

    const int tid = threadIdx.x;
    const int a_row = tid >> 1;
    const int a_col = (tid & 1) * 32;
    const int b_kr  = tid >> 2;
    const int b_nc  = (tid & 3) * 32;
    // rows >= cnt read stale-but-finite scratch; their outputs are never stored
    const __half* agp = g_hf + ((size_t)e * CAP + mb + a_row) * HH + a_col;
    const __half* wbp = g_w2f + (size_t)e * HH * DD + (size_t)b_kr * DD + nb + b_nc;
    const uint32_t aoff = (a_row * LDAS + a_col) * 2;
    const uint32_t boff = (b_kr * LDBS + b_nc) * 2;

    const int w = tid >> 5, lane = tid & 31;
    const int wm = (w >> 2) * 64, wn = (w & 3) * 32;
    const int g = lane >> 2, tq = lane & 3;
    const int alr = lane & 15, ahc = (lane >> 4) * 8;
    uint32_t aoffs[4], boffs[2];
    #pragma unroll
    for (int mf = 0; mf < 4; mf++)
        aoffs[mf] = ((wm + mf * 16 + alr) * LDAS + ahc) * 2;
    #pragma unroll
    for (int ns = 0; ns < 2; ns++)
        boffs[ns] = (alr * LDBS + wn + ns * 16 + ahc) * 2;

    float acc[4][4][4];
    #pragma unroll
    for (int a = 0; a < 4; a++)
        #pragma unroll
        for (int b = 0; b < 4; b++)
            #pragma unroll
            for (int c = 0; c < 4; c++) acc[a][b][c] = 0.f;

    const int NS = HH / BK;   // 32
    #pragma unroll
    for (int p = 0; p < NSTG - 1; p++) {
        const int kt = p * BK;
        const uint32_t ao = p * ASTB + aoff, bo = p * BSTB + boff;
        #pragma unroll
        for (int q = 0; q < 4; q++) {
            cp16(sA + ao + q * 16, agp + kt + q * 8);
            cp16(sB + bo + q * 16, wbp + (size_t)kt * DD + q * 8);
        }
        CP_COMMIT();
    }
    int buf = 0;
    for (int s = 0; s < NS; s++) {
        CP_WAIT1();
        __syncthreads();
        if (s + NSTG - 1 < NS) {
            const int p = s + NSTG - 1;
            const int kt = p * BK;
            int pb = p % NSTG;
            const uint32_t ao = pb * ASTB + aoff, bo = pb * BSTB + boff;
            #pragma unroll
            for (int q = 0; q < 4; q++) {
                cp16(sA + ao + q * 16, agp + kt + q * 8);
                cp16(sB + bo + q * 16, wbp + (size_t)kt * DD + q * 8);
            }
        }
        CP_COMMIT();

        const uint32_t Ab = sA + buf * ASTB;
        const uint32_t Bb = sB + buf * BSTB;
        #pragma unroll
        for (int kk = 0; kk < BK; kk += 16) {
            uint32_t ah[4][4], bfr[2][4];
            #pragma unroll
            for (int mf = 0; mf < 4; mf++) ldsm_x4(ah[mf], Ab + aoffs[mf] + kk * 2);
            #pragma unroll
            for (int ns = 0; ns < 2; ns++) ldsm_x4_t(bfr[ns], Bb + boffs[ns] + kk * (LDBS * 2));
            #pragma unroll
            for (int mf = 0; mf < 4; mf++)
                #pragma unroll
                for (int nf = 0; nf < 4; nf++)
                    mma_f16(acc[mf][nf], ah[mf], &bfr[nf >> 1][(nf & 1) * 2]);
        }
        if (++buf == NSTG) buf = 0;
    }

    // epilogue: +b2, * gate, vector red into out
    #pragma unroll
    for (int mf = 0; mf < 4; mf++) {
        #pragma unroll
        for (int rr = 0; rr < 2; rr++) {
            int m = mb + wm + mf * 16 + g + rr * 8;
            if (m >= cnt) continue;
            float gate = g_gate[e * CAP + m];
            int   tokid = g_tok[e * CAP + m];
            float* orow = out + (size_t)tokid * DD + nb;
            #pragma unroll
            for (int nf = 0; nf < 4; nf++) {
                int c = wn + nf * 8 + 2 * tq;
                red_v2(&orow[c],
                       (acc[mf][nf][rr * 2 + 0] + b2[e * DD + nb + c]) * gate,
                       (acc[mf][nf][rr * 2 + 1] + b2[e * DD + nb + c + 1]) * gate);
            }
        }
    }
}

// ---------------- launch ----------------
extern "C" void kernel_launch(void* const* d_in, const int* in_sizes, int n_in,
                              void* d_out, int out_size) {
    const float* x  = (const float*)d_in[0];
    const float* Wr = (const float*)d_in[1];
    const float* br = (const float*)d_in[2];
    const float* W1 = (const float*)d_in[3];
    const float* b1 = (const float*)d_in[4];
    const float* W2 = (const float*)d_in[5];
    const float* b2 = (const float*)d_in[6];
    float* out = (float*)d_out;

    cudaFuncSetAttribute(k_gemm1, cudaFuncAttributeMaxDynamicSharedMemorySize, SMEM_DYN);
    cudaFuncSetAttribute(k_gemm2, cudaFuncAttributeMaxDynamicSharedMemorySize, SMEM_DYN);

    k_zout<<<(NTOK * DD / 4) / 256, 256>>>(out);            // 1
    k_cvtw<<<8192, 256>>>(W1, W2);                          // 2
    k_router<<<NTOK / (RTB / 32), RTB>>>(x, Wr, br);        // 3
    k_gemm1<<<dim3(HH / BN, CAP / BM, EE), NT, SMEM_DYN>>>(b1);        // 4
    k_gemm2<<<dim3(DD / BN, CAP / BM, EE), NT, SMEM_DYN>>>(b2, out);   // 5
}

// round 16
// speedup vs baseline: 1.2113x; 1.2113x over previous
#include <cuda_runtime.h>
#include <cuda_bf16.h>
#include <cuda_fp16.h>
#include <stdint.h>
#include <math.h>

// Problem constants
#define NTOK 4096
#define DD   1024
#define EE   8
#define HH   2048
#define CAP  4096

// GEMM tiling (R10 configuration — verified local optimum)
#define BM 128
#define BN 128
#define BK 32
#define LDAS 40          // BK + 8 pad (fp16 elems); 80B rows
#define LDBS 136         // BN + 8 pad; 272B rows
#define NT 256
#define NSTG 4
#define ASTB (BM * LDAS * 2)   // 10240 B per A stage
#define BSTB (BK * LDBS * 2)   // 8704 B per B stage
#define SMEM_DYN (NSTG * (ASTB + BSTB))   // 75776 B

// prep kernel
#define RBLK 512                // router blocks (8 tokens each)
#define CBLK 8192               // cvt/zero blocks
#define WRD (DD + 4)            // padded smem row stride for wrt[e][*]

// ---------------- static scratch (no allocations allowed) ----------------
__device__ int   g_cnt[EE];
__device__ int   g_tok[EE * CAP];
__device__ float g_gate[EE * CAP];
__device__ __half g_xf[(size_t)NTOK * DD];          // 8 MB
__device__ __half g_w1f[(size_t)EE * DD * HH];      // 32 MB
__device__ __half g_w2f[(size_t)EE * HH * DD];      // 32 MB
__device__ __half g_hf[(size_t)EE * CAP * HH];      // 128 MB

// ---------------- init: zero expert counters (must precede router atomics) ----------------
__global__ void k_init() {
    if (threadIdx.x < EE) g_cnt[threadIdx.x] = 0;
}

// ---------------- fused prep: router ∥ weight-cvt ∥ out-zero ----------------
__global__ __launch_bounds__(256) void k_prep(const float* __restrict__ x,
                                              const float* __restrict__ Wr,
                                              const float* __restrict__ br,
                                              const float* __restrict__ W1,
                                              const float* __restrict__ W2,
                                              float* __restrict__ out) {
    __shared__ float wrt[EE * WRD];
    const int tid = threadIdx.x;

    if (blockIdx.x < RBLK) {
        // ---- router branch: 8 warps = 8 tokens; Wr staged transposed in smem ----
        for (int idx = tid; idx < DD * EE / 4; idx += 256) {
            float4 v = reinterpret_cast<const float4*>(Wr)[idx];
            int d = idx >> 1, eb = (idx & 1) * 4;
            wrt[(eb + 0) * WRD + d] = v.x;
            wrt[(eb + 1) * WRD + d] = v.y;
            wrt[(eb + 2) * WRD + d] = v.z;
            wrt[(eb + 3) * WRD + d] = v.w;
        }
        __syncthreads();

        const int t = blockIdx.x * 8 + (tid >> 5);
        const int lane = tid & 31;
        const float4* xr = reinterpret_cast<const float4*>(x + (size_t)t * DD);
        uint2* xo = reinterpret_cast<uint2*>(g_xf + (size_t)t * DD);

        float acc[EE];
        #pragma unroll
        for (int e = 0; e < EE; e++) acc[e] = 0.f;

        #pragma unroll
        for (int i = 0; i < 8; i++) {
            const int c = lane + i * 32;
            float4 v = xr[c];
            __half2 lo = __float22half2_rn(make_float2(v.x, v.y));
            __half2 hi = __float22half2_rn(make_float2(v.z, v.w));
            uint2 o;
            o.x = *reinterpret_cast<uint32_t*>(&lo);
            o.y = *reinterpret_cast<uint32_t*>(&hi);
            xo[c] = o;
            #pragma unroll
            for (int e = 0; e < EE; e++) {
                const float4 wv = *reinterpret_cast<const float4*>(&wrt[e * WRD + c * 4]);
                acc[e] = fmaf(v.x, wv.x, acc[e]);
                acc[e] = fmaf(v.y, wv.y, acc[e]);
                acc[e] = fmaf(v.z, wv.z, acc[e]);
                acc[e] = fmaf(v.w, wv.w, acc[e]);
            }
        }
        #pragma unroll
        for (int off = 16; off; off >>= 1)
            #pragma unroll
            for (int e = 0; e < EE; e++)
                acc[e] += __shfl_xor_sync(0xffffffffu, acc[e], off);

        if (lane == 0) {
            #pragma unroll
            for (int e = 0; e < EE; e++) acc[e] += br[e];
            float v0 = -3.4e38f; int i0 = 0;
            #pragma unroll
            for (int e = 0; e < EE; e++) if (acc[e] > v0) { v0 = acc[e]; i0 = e; }
            float v1 = -3.4e38f; int i1 = 0;
            #pragma unroll
            for (int e = 0; e < EE; e++) if (e != i0 && acc[e] > v1) { v1 = acc[e]; i1 = e; }
            float eb  = expf(v1 - v0);
            float inv = 1.f / (1.f + eb);
            int p0 = atomicAdd(&g_cnt[i0], 1);
            g_tok[i0 * CAP + p0] = t; g_gate[i0 * CAP + p0] = inv;
            int p1 = atomicAdd(&g_cnt[i1], 1);
            g_tok[i1 * CAP + p1] = t; g_gate[i1 * CAP + p1] = eb * inv;
        }
    } else {
        // ---- streaming branch: W1,W2 -> fp16 + zero out ----
        const int n1 = EE * DD * HH / 4;          // float4 per weight tensor
        const int nz = NTOK * DD / 4;             // float4 in out
        const int total = 2 * n1 + nz;
        const int b = blockIdx.x - RBLK;
        for (int i = b * 256 + tid; i < total; i += CBLK * 256) {
            if (i < 2 * n1) {
                const float* src = (i < n1) ? W1 : W2;
                __half* dst = (i < n1) ? g_w1f : g_w2f;
                int j = (i < n1) ? i : i - n1;
                float4 v = reinterpret_cast<const float4*>(src)[j];
                __half2 lo = __float22half2_rn(make_float2(v.x, v.y));
                __half2 hi = __float22half2_rn(make_float2(v.z, v.w));
                uint2 o;
                o.x = *reinterpret_cast<uint32_t*>(&lo);
                o.y = *reinterpret_cast<uint32_t*>(&hi);
                reinterpret_cast<uint2*>(dst)[j] = o;
            } else {
                reinterpret_cast<float4*>(out)[i - 2 * n1] = make_float4(0.f, 0.f, 0.f, 0.f);
            }
        }
    }
}

// ---------------- asm helpers ----------------
__device__ __forceinline__ void mma_f16(float c[4], const uint32_t a[4], const uint32_t b[2]) {
    asm volatile(
        "mma.sync.aligned.m16n8k16.row.col.f32.f16.f16.f32 "
        "{%0,%1,%2,%3}, {%4,%5,%6,%7}, {%8,%9}, {%0,%1,%2,%3};\n"
        : "+f"(c[0]), "+f"(c[1]), "+f"(c[2]), "+f"(c[3])
        : "r"(a[0]), "r"(a[1]), "r"(a[2]), "r"(a[3]), "r"(b[0]), "r"(b[1]));
}
__device__ __forceinline__ void ldsm_x4(uint32_t r[4], uint32_t addr) {
    asm volatile("ldmatrix.sync.aligned.m8n8.x4.shared.b16 {%0,%1,%2,%3}, [%4];\n"
        : "=r"(r[0]), "=r"(r[1]), "=r"(r[2]), "=r"(r[3]) : "r"(addr));
}
__device__ __forceinline__ void ldsm_x4_t(uint32_t r[4], uint32_t addr) {
    asm volatile("ldmatrix.sync.aligned.m8n8.x4.trans.shared.b16 {%0,%1,%2,%3}, [%4];\n"
        : "=r"(r[0]), "=r"(r[1]), "=r"(r[2]), "=r"(r[3]) : "r"(addr));
}
__device__ __forceinline__ void cp16(uint32_t dst, const void* src) {
    asm volatile("cp.async.cg.shared.global [%0], [%1], 16;\n" :: "r"(dst), "l"(src));
}
__device__ __forceinline__ void cp16z(uint32_t dst, const void* src, uint32_t sz) {
    asm volatile("cp.async.cg.shared.global [%0], [%1], 16, %2;\n" :: "r"(dst), "l"(src), "r"(sz));
}
__device__ __forceinline__ void red_v2(float* addr, float v0, float v1) {
    asm volatile("red.global.add.v2.f32 [%0], {%1, %2};\n"
        :: "l"(addr), "f"(v0), "f"(v1) : "memory");
}
#define CP_COMMIT() asm volatile("cp.async.commit_group;\n")
#define CP_WAIT2()  asm volatile("cp.async.wait_group 2;\n")

// ---------------- GEMM1: H = relu(Xg @ W1 + b1), fp16 MMA, 4-stage pipe (R10) ----------------
__global__ __launch_bounds__(NT, 2) void k_gemm1(const float* __restrict__ b1) {
    const int e   = blockIdx.z;
    const int cnt = g_cnt[e];
    const int mb  = blockIdx.y * BM;
    if (mb >= cnt) return;
    const int nb  = blockIdx.x * BN;

    extern __shared__ char dynsmem[];
    const uint32_t sA = (uint32_t)__cvta_generic_to_shared(dynsmem);
    const uint32_t sB = sA + NSTG * ASTB;
    __shared__ int stok[BM];

    const int tid = threadIdx.x;
    if (tid < BM) {
        int m = mb + tid;
        stok[tid] = (m < cnt) ? g_tok[e * CAP + m] : -1;
    }
    __syncthreads();

    const int a_row = tid >> 1;
    const int a_col = (tid & 1) * 16;
    const int b_kr  = tid >> 3;
    const int b_nc  = (tid & 7) * 16;
    const int atok  = stok[a_row];
    const uint32_t a_sz = (atok >= 0) ? 16u : 0u;
    const __half* agp = g_xf + (atok >= 0 ? (size_t)atok * DD + a_col : 0);
    const __half* wbp = g_w1f + (size_t)e * DD * HH + (size_t)b_kr * HH + nb + b_nc;
    const uint32_t aoff = (a_row * LDAS + a_col) * 2;
    const uint32_t boff = (b_kr * LDBS + b_nc) * 2;

    const int w = tid >> 5, lane = tid & 31;
    const int wm = (w >> 2) * 64, wn = (w & 3) * 32;
    const int g = lane >> 2, tq = lane & 3;
    const int alr = lane & 15, ahc = (lane >> 4) * 8;
    uint32_t aoffs[4], boffs[2];
    #pragma unroll
    for (int mf = 0; mf < 4; mf++)
        aoffs[mf] = ((wm + mf * 16 + alr) * LDAS + ahc) * 2;
    #pragma unroll
    for (int ns = 0; ns < 2; ns++)
        boffs[ns] = (alr * LDBS + wn + ns * 16 + ahc) * 2;

    float acc[4][4][4];
    #pragma unroll
    for (int a = 0; a < 4; a++)
        #pragma unroll
        for (int b = 0; b < 4; b++)
            #pragma unroll
            for (int c = 0; c < 4; c++) acc[a][b][c] = 0.f;

    const int NS = DD / BK;   // 32
    #pragma unroll
    for (int p = 0; p < NSTG - 1; p++) {
        const int kt = p * BK;
        const uint32_t ao = p * ASTB + aoff, bo = p * BSTB + boff;
        cp16z(sA + ao, agp + kt, a_sz);
        cp16z(sA + ao + 16, agp + kt + 8, a_sz);
        cp16(sB + bo, wbp + (size_t)kt * HH);
        cp16(sB + bo + 16, wbp + (size_t)kt * HH + 8);
        CP_COMMIT();
    }
    for (int s = 0; s < NS; s++) {
        CP_WAIT2();
        __syncthreads();
        if (s + NSTG - 1 < NS) {
            const int p = s + NSTG - 1;
            const int kt = p * BK;
            const uint32_t ao = (p & 3) * ASTB + aoff, bo = (p & 3) * BSTB + boff;
            cp16z(sA + ao, agp + kt, a_sz);
            cp16z(sA + ao + 16, agp + kt + 8, a_sz);
            cp16(sB + bo, wbp + (size_t)kt * HH);
            cp16(sB + bo + 16, wbp + (size_t)kt * HH + 8);
        }
        CP_COMMIT();

        const uint32_t Ab = sA + (s & 3) * ASTB;
        const uint32_t Bb = sB + (s & 3) * BSTB;
        #pragma unroll
        for (int kk = 0; kk < BK; kk += 16) {
            uint32_t ah[4][4], bfr[2][4];
            #pragma unroll
            for (int mf = 0; mf < 4; mf++) ldsm_x4(ah[mf], Ab + aoffs[mf] + kk * 2);
            #pragma unroll
            for (int ns = 0; ns < 2; ns++) ldsm_x4_t(bfr[ns], Bb + boffs[ns] + kk * (LDBS * 2));
            #pragma unroll
            for (int mf = 0; mf < 4; mf++)
                #pragma unroll
                for (int nf = 0; nf < 4; nf++)
                    mma_f16(acc[mf][nf], ah[mf], &bfr[nf >> 1][(nf & 1) * 2]);
        }
    }

    // epilogue: +b1, relu, store fp16 h
    #pragma unroll
    for (int mf = 0; mf < 4; mf++) {
        #pragma unroll
        for (int rr = 0; rr < 2; rr++) {
            int m = mb + wm + mf * 16 + g + rr * 8;
            if (m >= cnt) continue;
            size_t base = ((size_t)e * CAP + m) * HH + nb;
            #pragma unroll
            for (int nf = 0; nf < 4; nf++) {
                int c = wn + nf * 8 + 2 * tq;
                float v0 = fmaxf(acc[mf][nf][rr * 2 + 0] + b1[e * HH + nb + c], 0.f);
                float v1 = fmaxf(acc[mf][nf][rr * 2 + 1] + b1[e * HH + nb + c + 1], 0.f);
                __half2 pr = __float22half2_rn(make_float2(v0, v1));
                *reinterpret_cast<__half2*>(&g_hf[base + c]) = pr;
            }
        }
    }
}

// ---------------- GEMM2: out += gate * (H @ W2 + b2), fp16 MMA, red.v2 epilogue (R10) ----------------
__global__ __launch_bounds__(NT, 2) void k_gemm2(const float* __restrict__ b2,
                                                 float* __restrict__ out) {
    const int e   = blockIdx.z;
    const int cnt = g_cnt[e];
    const int mb  = blockIdx.y * BM;
    if (mb >= cnt) return;
    const int nb  = blockIdx.x * BN;

    extern __shared__ char dynsmem[];
    const uint32_t sA = (uint32_t)__cvta_generic_to_shared(dynsmem);
    const uint32_t sB = sA + NSTG * ASTB;

    const int tid = threadIdx.x;
    const int a_row = tid >> 1;
    const int a_col = (tid & 1) * 16;
    const int b_kr  = tid >> 3;
    const int b_nc  = (tid & 7) * 16;
    // rows >= cnt read stale-but-finite scratch; their outputs are never stored
    const __half* agp = g_hf + ((size_t)e * CAP + mb + a_row) * HH + a_col;
    const __half* wbp = g_w2f + (size_t)e * HH * DD + (size_t)b_kr * DD + nb + b_nc;
    const uint32_t aoff = (a_row * LDAS + a_col) * 2;
    const uint32_t boff = (b_kr * LDBS + b_nc) * 2;

    const int w = tid >> 5, lane = tid & 31;
    const int wm = (w >> 2) * 64, wn = (w & 3) * 32;
    const int g = lane >> 2, tq = lane & 3;
    const int alr = lane & 15, ahc = (lane >> 4) * 8;
    uint32_t aoffs[4], boffs[2];
    #pragma unroll
    for (int mf = 0; mf < 4; mf++)
        aoffs[mf] = ((wm + mf * 16 + alr) * LDAS + ahc) * 2;
    #pragma unroll
    for (int ns = 0; ns < 2; ns++)
        boffs[ns] = (alr * LDBS + wn + ns * 16 + ahc) * 2;

    float acc[4][4][4];
    #pragma unroll
    for (int a = 0; a < 4; a++)
        #pragma unroll
        for (int b = 0; b < 4; b++)
            #pragma unroll
            for (int c = 0; c < 4; c++) acc[a][b][c] = 0.f;

    const int NS = HH / BK;   // 64
    #pragma unroll
    for (int p = 0; p < NSTG - 1; p++) {
        const int kt = p * BK;
        const uint32_t ao = p * ASTB + aoff, bo = p * BSTB + boff;
        cp16(sA + ao, agp + kt);
        cp16(sA + ao + 16, agp + kt + 8);
        cp16(sB + bo, wbp + (size_t)kt * DD);
        cp16(sB + bo + 16, wbp + (size_t)kt * DD + 8);
        CP_COMMIT();
    }
    for (int s = 0; s < NS; s++) {
        CP_WAIT2();
        __syncthreads();
        if (s + NSTG - 1 < NS) {
            const int p = s + NSTG - 1;
            const int kt = p * BK;
            const uint32_t ao = (p & 3) * ASTB + aoff, bo = (p & 3) * BSTB + boff;
            cp16(sA + ao, agp + kt);
            cp16(sA + ao + 16, agp + kt + 8);
            cp16(sB + bo, wbp + (size_t)kt * DD);
            cp16(sB + bo + 16, wbp + (size_t)kt * DD + 8);
        }
        CP_COMMIT();

        const uint32_t Ab = sA + (s & 3) * ASTB;
        const uint32_t Bb = sB + (s & 3) * BSTB;
        #pragma unroll
        for (int kk = 0; kk < BK; kk += 16) {
            uint32_t ah[4][4], bfr[2][4];
            #pragma unroll
            for (int mf = 0; mf < 4; mf++) ldsm_x4(ah[mf], Ab + aoffs[mf] + kk * 2);
            #pragma unroll
            for (int ns = 0; ns < 2; ns++) ldsm_x4_t(bfr[ns], Bb + boffs[ns] + kk * (LDBS * 2));
            #pragma unroll
            for (int mf = 0; mf < 4; mf++)
                #pragma unroll
                for (int nf = 0; nf < 4; nf++)
                    mma_f16(acc[mf][nf], ah[mf], &bfr[nf >> 1][(nf & 1) * 2]);
        }
    }

    // epilogue: +b2, * gate, vector red into out
    #pragma unroll
    for (int mf = 0; mf < 4; mf++) {
        #pragma unroll
        for (int rr = 0; rr < 2; rr++) {
            int m = mb + wm + mf * 16 + g + rr * 8;
            if (m >= cnt) continue;
            float gate = g_gate[e * CAP + m];
            int   tokid = g_tok[e * CAP + m];
            float* orow = out + (size_t)tokid * DD + nb;
            #pragma unroll
            for (int nf = 0; nf < 4; nf++) {
                int c = wn + nf * 8 + 2 * tq;
                red_v2(&orow[c],
                       (acc[mf][nf][rr * 2 + 0] + b2[e * DD + nb + c]) * gate,
                       (acc[mf][nf][rr * 2 + 1] + b2[e * DD + nb + c + 1]) * gate);
            }
        }
    }
}

// ---------------- launch ----------------
extern "C" void kernel_launch(void* const* d_in, const int* in_sizes, int n_in,
                              void* d_out, int out_size) {
    const float* x  = (const float*)d_in[0];
    const float* Wr = (const float*)d_in[1];
    const float* br = (const float*)d_in[2];
    const float* W1 = (const float*)d_in[3];
    const float* b1 = (const float*)d_in[4];
    const float* W2 = (const float*)d_in[5];
    const float* b2 = (const float*)d_in[6];
    float* out = (float*)d_out;

    cudaFuncSetAttribute(k_gemm1, cudaFuncAttributeMaxDynamicSharedMemorySize, SMEM_DYN);
    cudaFuncSetAttribute(k_gemm2, cudaFuncAttributeMaxDynamicSharedMemorySize, SMEM_DYN);

    k_init<<<1, 32>>>();                                                 // 1
    k_prep<<<RBLK + CBLK, 256>>>(x, Wr, br, W1, W2, out);                // 2 (router ∥ cvt ∥ zero)
    k_gemm1<<<dim3(HH / BN, CAP / BM, EE), NT, SMEM_DYN>>>(b1);          // 3
    k_gemm2<<<dim3(DD / BN, CAP / BM, EE), NT, SMEM_DYN>>>(b2, out);     // 4
}